// round 13
// baseline (speedup 1.0000x reference)
#include <cuda_runtime.h>
#include <cuda_bf16.h>
#include <cstdint>

// Problem constants
#define Bb    32
#define Ll    4096
#define Cc    128
#define OUTD  257          // 1 delta + 128 probs + 128 amt
#define CL    128          // stored rows per chunk (one chunk = one 64-thread block)
#define HALO  192          // 0.9^192 ~ 1.6e-9
#define WIN   (CL + HALO)  // 320

#define MOM   0.9f
#define OMM   0.1f

__global__ __launch_bounds__(64, 16)
void mpe_kernel(const float* __restrict__ ts,
                const int*   __restrict__ labels,
                const float* __restrict__ amounts,
                float*       __restrict__ out)
{
    __shared__ uint2 s_la[WIN];   // .x = label, .y = bits(0.1*amount)
    __shared__ float s_dl[WIN];   // clipped deltas

    const int chunk = blockIdx.x;
    const int b     = blockIdx.y;
    const int t0    = chunk * CL;
    const int s0    = (t0 - HALO) > 0 ? (t0 - HALO) : 0;
    const int N     = t0 + CL - s0;
    const int warm  = t0 - s0;            // 0 (chunk 0), 128 (chunk 1), 192 (rest)
    const int tid   = threadIdx.x;
    const int w     = tid >> 5;           // warp 0: ch 0-63 (+delta); warp 1: ch 64-127
    const int lane  = tid & 31;

    const float* tsb = ts      + (size_t)b * Ll;
    const int*   lb  = labels  + (size_t)b * Ll;
    const float* ab  = amounts + (size_t)b * Ll;

    // ---- cooperative preload (amounts pre-scaled by 0.1) ----
    for (int i = tid; i < N; i += 64) {
        const int g = s0 + i;
        s_la[i] = make_uint2((unsigned)lb[g], __float_as_uint(OMM * ab[g]));
        float d = 0.0f;
        if (g > 0) d = fminf(tsb[g] - tsb[g - 1], 100.0f);
        s_dl[i] = d;
    }
    __syncthreads();   // the ONLY block-wide barrier

    // ---- per-thread state: 2 channels, strided for coalesced STG ----
    const int c0 = w * 64 + lane;         // k = 0
    const int c1 = c0 + 32;               // k = 1
    float p0 = 0.0f, a0 = 0.0f, p1 = 0.0f, a1 = 0.0f, dcar = 0.0f;
    int   i0 = 0;

    if (s0 == 0) {
        // Window starts at the true sequence start: EXACT carry-init with x0
        // (reference scan has carry = x[0]; x0's coefficient is 0.9^n, not
        //  0.1*0.9^n — zero-init here caused the R12 clip-boundary failure).
        const uint2 v0 = s_la[0];
        const bool e0 = ((int)v0.x == c0);
        const bool e1 = ((int)v0.x == c1);
        const float am0 = 10.0f * __uint_as_float(v0.y);   // true amount
        p0 = e0 ? 1.0f : 0.0f;  a0 = e0 ? am0 : 0.0f;
        p1 = e1 ? 1.0f : 0.0f;  a1 = e1 ? am0 : 0.0f;
        // delta carry: dl[0] == 0 -> dcar = 0 is exact
        i0 = 1;                            // x0 consumed as the carry
    }

    // dense branchless warm-up (no stores, no divides); exact when s0==0,
    // truncation <= 0.9^192 otherwise
    #pragma unroll 8
    for (int i = i0; i < warm; i++) {
        const uint2 v = s_la[i];
        const bool e0 = ((int)v.x == c0);
        const bool e1 = ((int)v.x == c1);
        const float am = __uint_as_float(v.y);
        p0 = MOM * p0 + (e0 ? OMM : 0.0f);
        a0 = MOM * a0 + (e0 ? am  : 0.0f);
        p1 = MOM * p1 + (e1 ? OMM : 0.0f);
        a1 = MOM * a1 + (e1 ? am  : 0.0f);
        if (w == 0) dcar = MOM * dcar + OMM * s_dl[i];
    }

    // ratio state: r == a/p, refreshed only at hits (p >= 0.1 there)
    float r0 = __fdividef(a0, fmaxf(p0, 1e-30f));   // a==0 when p==0 -> r=0
    float r1 = __fdividef(a1, fmaxf(p1, 1e-30f));

    // ---- 128 stored rows: direct coalesced STG.32, no staging, no barriers ----
    float* orow = out + (size_t)(b * Ll + t0) * OUTD;
    const int hk0 = 2 * w;                // this warp's sub-banks: hk0, hk0+1
    #pragma unroll 4
    for (int j = 0; j < CL; j++) {
        const uint2 v  = s_la[warm + j];
        const int  lab = (int)v.x;
        const float am = __uint_as_float(v.y);
        const bool e0 = (lab == c0);
        const bool e1 = (lab == c1);
        p0 = MOM * p0 + (e0 ? OMM : 0.0f);
        a0 = MOM * a0 + (e0 ? am  : 0.0f);
        p1 = MOM * p1 + (e1 ? OMM : 0.0f);
        a1 = MOM * a1 + (e1 ? am  : 0.0f);

        // hit sub-bank is warp-uniform (broadcast value) -> uniform branch,
        // single predicated divide for the one hitting lane (p >= 0.1 at a hit)
        const int hk = lab >> 5;
        if (hk == hk0)          { if (e0) r0 = __fdividef(a0, p0); }
        else if (hk == hk0 + 1) { if (e1) r1 = __fdividef(a1, p1); }

        // amt = a / max(p,1e-6) == min(a/p, 1e6*a)  (exact identity)
        const float amt0 = fminf(r0, 1e6f * a0);
        const float amt1 = fminf(r1, 1e6f * a1);

        orow[1 + c0]      = p0;            // probs (sum == 1, skip norm)
        orow[1 + c1]      = p1;
        orow[1 + Cc + c0] = amt0;
        orow[1 + Cc + c1] = amt1;

        if (w == 0) {
            dcar = MOM * dcar + OMM * s_dl[warm + j];
            if (lane == 0) orow[0] = dcar;
        }
        orow += OUTD;
    }
}

extern "C" void kernel_launch(void* const* d_in, const int* in_sizes, int n_in,
                              void* d_out, int out_size)
{
    const float* ts      = (const float*)d_in[0];
    const int*   labels  = (const int*)  d_in[1];
    const float* amounts = (const float*)d_in[2];
    float* out = (float*)d_out;

    dim3 grid(Ll / CL, Bb);   // (32, 32) = 1024 blocks
    dim3 block(64);
    mpe_kernel<<<grid, block>>>(ts, labels, amounts, out);
}

// round 14
// speedup vs baseline: 1.4258x; 1.4258x over previous
#include <cuda_runtime.h>
#include <cuda_bf16.h>
#include <cstdint>

// Problem constants
#define Bb    32
#define Ll    4096
#define Cc    128
#define OUTD  257          // 1 delta + 128 probs + 128 amt
#define CL    256          // stored steps per block
#define HALO  192          // 0.9^192 ~ 1.6e-9 -> below fp32 noise
#define MAXN  (CL + HALO)  // 448
#define TT    8            // rows per staged tile
#define NTILE (CL / TT)    // 32
#define NBUF  6            // staging ring depth (5 copies in flight)

#define MOM   0.9f
#define OMM   0.1f

__device__ __forceinline__ uint32_t smem_u32(const void* p) {
    uint32_t a;
    asm("{ .reg .u64 t; cvta.to.shared.u64 t, %1; cvt.u32.u64 %0, t; }"
        : "=r"(a) : "l"(p));
    return a;
}

__global__ __launch_bounds__(160, 4)
void mpe_kernel(const float* __restrict__ ts,
                const int*   __restrict__ labels,
                const float* __restrict__ amounts,
                float*       __restrict__ out)
{
    __shared__ uint2 s_la[MAXN];                           // .x=label, .y=bits(0.1*amount)
    __shared__ float s_dl[MAXN];                           // clipped deltas
    __shared__ __align__(16) float s_out[NBUF][TT * OUTD]; // staging ring

    const int chunk = blockIdx.x;
    const int b     = blockIdx.y;
    const int t0    = chunk * CL;
    const int s0    = (t0 - HALO) > 0 ? (t0 - HALO) : 0;
    const int N     = t0 + CL - s0;
    const int warm  = t0 - s0;                             // 0 (chunk 0) or 192
    const int tid   = threadIdx.x;

    const float* tsb = ts      + (size_t)b * Ll;
    const int*   lb  = labels  + (size_t)b * Ll;
    const float* ab  = amounts + (size_t)b * Ll;

    // L2 evict_last policy for output: keep output lines resident in L2 so
    // the dirty write-back stream (~75 MB/launch, the measured 28 us wall)
    // collapses to the ~9 MB capacity overflow.
    uint64_t pol;
    asm("createpolicy.fractional.L2::evict_last.b64 %0, 1.0;" : "=l"(pol));

    // ---- cooperative preload (amounts pre-scaled by 0.1) ----
    for (int i = tid; i < N; i += blockDim.x) {
        const int g = s0 + i;
        s_la[i] = make_uint2((unsigned)lb[g], __float_as_uint(OMM * ab[g]));
        float d = 0.0f;
        if (g > 0) d = fminf(tsb[g] - tsb[g - 1], 100.0f);
        s_dl[i] = d;
    }
    __syncthreads();

    // ---- per-thread state ----
    float p = 0.0f, a = 0.0f, dcar = 0.0f;
    const int c = tid;

    if (tid < Cc) {
        if (warm == 0) {
            // chunk 0 carry-init: row 0 then emits exactly x0
            const uint2 la0 = s_la[0];
            const bool eq0 = ((int)la0.x == c);
            p = eq0 ? 1.0f : 0.0f;
            a = eq0 ? 10.0f * __uint_as_float(la0.y) : 0.0f;
        } else {
            // dense branchless warm-up
            #pragma unroll 8
            for (int i = 0; i < warm; i++) {
                const uint2 v = s_la[i];
                const bool eq = ((int)v.x == c);
                p = MOM * p + (eq ? OMM : 0.0f);
                a = MOM * a + (eq ? __uint_as_float(v.y) : 0.0f);
            }
        }
    } else if (tid == Cc) {
        #pragma unroll 8
        for (int i = 0; i < warm; i++)
            dcar = MOM * dcar + OMM * s_dl[i];
    }

    // ---- stored steps: dense scan into 6-deep staging ring, async drain ----
    const char* gbase = (const char*)(out + (size_t)(b * Ll + t0) * OUTD);
    for (int tile = 0; tile < NTILE; tile++) {
        float* ob = s_out[tile % NBUF];
        const int base = warm + tile * TT;

        if (tid < Cc) {
            const uint2* la = s_la + base;
            #pragma unroll
            for (int j = 0; j < TT; j++) {
                const uint2 v = la[j];
                const bool eq = ((int)v.x == c);
                p = MOM * p + (eq ? OMM : 0.0f);
                a = MOM * a + (eq ? __uint_as_float(v.y) : 0.0f);
                ob[j * OUTD + 1 + c]      = p;                              // probs (sum==1)
                ob[j * OUTD + 1 + Cc + c] = __fdividef(a, fmaxf(p, 1e-6f)); // amt
            }
        } else if (tid == Cc) {
            const float* dl = s_dl + base;
            #pragma unroll
            for (int j = 0; j < TT; j++) {
                dcar = MOM * dcar + OMM * dl[j];
                ob[j * OUTD] = dcar;
            }
        }
        __syncthreads();   // tile fully written

        if (tid == Cc + 1) {
            asm volatile("fence.proxy.async.shared::cta;" ::: "memory");
            const uint64_t gdst = (uint64_t)(gbase + (size_t)tile * TT * OUTD * 4);
            const uint32_t ssrc = smem_u32(ob);
            asm volatile("cp.async.bulk.global.shared::cta.bulk_group.L2::cache_hint "
                         "[%0], [%1], %2, %3;"
                         :: "l"(gdst), "r"(ssrc), "r"((uint32_t)(TT * OUTD * 4)), "l"(pol)
                         : "memory");
            asm volatile("cp.async.bulk.commit_group;" ::: "memory");
            // 5 copies in flight; buffer reused at (tile+1) is the one whose
            // copy completion this guarantees.
            asm volatile("cp.async.bulk.wait_group 5;" ::: "memory");
        }
        __syncthreads();   // reuse-safety broadcast
    }

    if (tid == Cc + 1)
        asm volatile("cp.async.bulk.wait_group 0;" ::: "memory");
    __syncthreads();       // keep smem alive until all copies land
}

extern "C" void kernel_launch(void* const* d_in, const int* in_sizes, int n_in,
                              void* d_out, int out_size)
{
    const float* ts      = (const float*)d_in[0];
    const int*   labels  = (const int*)  d_in[1];
    const float* amounts = (const float*)d_in[2];
    float* out = (float*)d_out;

    dim3 grid(Ll / CL, Bb);   // (16, 32) = 512 blocks
    dim3 block(160);
    mpe_kernel<<<grid, block>>>(ts, labels, amounts, out);
}